// round 11
// baseline (speedup 1.0000x reference)
#include <cuda_runtime.h>
#include <math.h>

#define T_STEPS 256
#define LLEN    1024
#define CIN     14
#define CCONV   32
#define H       128
#define G4H     512
#define NC      7
#define M_TOT   (T_STEPS*LLEN)   // 262144

typedef unsigned long long u64;
typedef unsigned int u32;

// packed f32x2 helpers (sm_103a FFMA2 — only reachable via PTX)
__device__ __forceinline__ u64 pack2(float x) {
    u64 r; asm("mov.b64 %0, {%1, %1};" : "=l"(r) : "f"(x)); return r;
}
__device__ __forceinline__ void fma2(u64& d, u64 a, u64 b) {
    asm("fma.rn.f32x2 %0, %1, %2, %3;" : "=l"(d) : "l"(a), "l"(b), "l"(d));
}
__device__ __forceinline__ void unpack2(float& lo, float& hi, u64 v) {
    asm("mov.b64 {%0, %1}, %2;" : "=f"(lo), "=f"(hi) : "l"(v));
}

__device__ __forceinline__ float fsig(float x) {          // sigmoid
    return __fdividef(1.f, 1.f + __expf(-x));
}
__device__ __forceinline__ float ftanh(float x) {         // tanh, safe at +-inf
    float t = __expf(2.f * x);
    return 1.f - __fdividef(2.f, t + 1.f);
}

// ---------------- scratch (device globals; allocation is banned) ----------
__device__ float g_cur1[(size_t)M_TOT * CCONV];   //  32 MB  conv spikes [row, 32]
__device__ float g_spk1[(size_t)M_TOT * H];       // 128 MB  layer-1 spikes [row, H]
__device__ float g_memsum[LLEN * H];
__device__ float g_part[256 * H];                 // BN partial sums
__device__ float g_wc1T[(CCONV + H) * G4H];       // fp32 [k][j]: 0..31 ih1, 32..159 hh1
__device__ float g_wc2T[(H + H) * G4H];           // fp32 [k][j]: 0..127 BN*ih2, 128..255 hh2
__device__ float g_bias1[G4H];                    // b_ih1 + b_hh1
__device__ float g_bias2[G4H];                    // b_ih2 + b_hh2 + BN-shift folded
__device__ float g_sa[H];                         // BN scale
__device__ float g_sbv[H];                        // BN shift

// ---------------- prep: static weight transposes + bias combine ------------
__global__ void prep0(const float* __restrict__ w_ih1, const float* __restrict__ w_hh1,
                      const float* __restrict__ b_ih1, const float* __restrict__ b_hh1,
                      const float* __restrict__ w_hh2) {
    int stride = gridDim.x * blockDim.x;
    int i0 = blockIdx.x * blockDim.x + threadIdx.x;
    for (int idx = i0; idx < (CCONV + H) * G4H; idx += stride) {
        int k = idx / G4H, j = idx % G4H;
        g_wc1T[idx] = (k < CCONV) ? w_ih1[j * CCONV + k] : w_hh1[j * H + (k - CCONV)];
    }
    for (int idx = i0; idx < H * G4H; idx += stride) {
        int k = idx / G4H, j = idx % G4H;
        g_wc2T[(H + k) * G4H + j] = w_hh2[j * H + k];
    }
    for (int idx = i0; idx < G4H; idx += stride)
        g_bias1[idx] = b_ih1[idx] + b_hh1[idx];
}

// ---------------- conv1d(k=3,pad=1) + Leaky spike ---------------------------
__global__ void __launch_bounds__(256) conv_spike(const float* __restrict__ x,
                                                  const float* __restrict__ conv_w,
                                                  const float* __restrict__ conv_b) {
    __shared__ float sw[3][CIN][CCONV];
    __shared__ float sb[CCONV];
    int tid = threadIdx.x;
    for (int i = tid; i < 3 * CIN * CCONV; i += 256) {
        int c = i % CCONV; int rem = i / CCONV; int ci = rem % CIN; int kk = rem / CIN;
        sw[kk][ci][c] = conv_w[(c * CIN + ci) * 3 + kk];
    }
    if (tid < CCONV) sb[tid] = conv_b[tid];
    __syncthreads();

    int gid = blockIdx.x * 256 + tid;   // over M_TOT
    int t = gid >> 10, l = gid & 1023;
    float acc[CCONV];
#pragma unroll
    for (int c = 0; c < CCONV; c++) acc[c] = sb[c];
#pragma unroll
    for (int kk = 0; kk < 3; kk++) {
        int ll = l + kk - 1;
        bool valid = (ll >= 0 && ll < LLEN);
        const float* xp = x + ((size_t)t * LLEN + (valid ? ll : 0)) * CIN;
#pragma unroll
        for (int ci = 0; ci < CIN; ci++) {
            float xv = valid ? xp[ci] : 0.f;
#pragma unroll
            for (int c = 0; c < CCONV; c++) acc[c] = fmaf(xv, sw[kk][ci][c], acc[c]);
        }
    }
    float4* outp = (float4*)&g_cur1[(size_t)gid * CCONV];
#pragma unroll
    for (int q = 0; q < 8; q++) {
        float4 v;
        v.x = (acc[q*4+0] - 1.0f) > 0.f ? 1.f : 0.f;
        v.y = (acc[q*4+1] - 1.0f) > 0.f ? 1.f : 0.f;
        v.z = (acc[q*4+2] - 1.0f) > 0.f ? 1.f : 0.f;
        v.w = (acc[q*4+3] - 1.0f) > 0.f ? 1.f : 0.f;
        outp[q] = v;
    }
}

// ---------------- persistent fused SLSTM scan -------------------------------
// 128 blocks x 128 threads; block owns 8 rows for ALL 256 steps. Thread owns
// 4 adjacent cols x 8 rows (FFMA2 row-pairs). First NCACHE weight k-rows live
// in SMEM; rest stream from L2 via LDG.128. Next step's input tile is
// prefetched into registers during the gemm (LDG latency hidden).
// inT stride 12: 16B-aligned row-pairs, reduced STS conflicts.
template<int KIN, int LAYER, int NCACHE>
__global__ void __launch_bounds__(128, 1) scan_all(const float* __restrict__ thr_p) {
    constexpr int KTOT = KIN + H;
    constexpr int NPF  = (KIN * 8) / 128;   // prefetch regs/thread: L1=2, L2=8
    constexpr int KSH  = (KIN == 32) ? 5 : 7;
    extern __shared__ float dsm[];
    float* swc  = dsm;                       // NCACHE * G4H  cached weights
    float* inT  = swc + NCACHE * G4H;        // KTOT * 12  [k][r] inputs then mem
    float* sG   = inT + KTOT * 12;           // 8 * G4H    gate pre-activations
    float* ssyn = sG + 8 * G4H;              // 8 * H
    float* msum = ssyn + 8 * H;              // 8 * H

    const float* __restrict__ wT = (LAYER == 1) ? g_wc1T : g_wc2T;
    const float* __restrict__ bi = (LAYER == 1) ? g_bias1 : g_bias2;
    const float* __restrict__ src = (LAYER == 1) ? g_cur1 : g_spk1;
    const int tid = threadIdx.x;             // owns cols 4*tid .. 4*tid+3
    const int row0 = blockIdx.x * 8;
    const float thr = *thr_p;
    const float4 bias = *(const float4*)&bi[4 * tid];

    // fill weight cache + zero state
    for (int e = tid; e < NCACHE * G4H; e += 128) swc[e] = wT[e];
    for (int e = tid; e < 8 * H; e += 128) { ssyn[e] = 0.f; msum[e] = 0.f; }
    for (int e = tid; e < 8 * H; e += 128) inT[(KIN + (e >> 3)) * 12 + (e & 7)] = 0.f;

    // prologue: load + store input tile for t = 0
    float pin[NPF];
#pragma unroll
    for (int s = 0; s < NPF; s++) {
        int idx = tid + (s << 7);
        int r = idx >> KSH, k = idx & (KIN - 1);
        pin[s] = src[((size_t)(0 * LLEN + row0 + r)) * KIN + k];
    }
#pragma unroll
    for (int s = 0; s < NPF; s++) {
        int idx = tid + (s << 7);
        int r = idx >> KSH, k = idx & (KIN - 1);
        inT[k * 12 + r] = pin[s];
    }
    __syncthreads();

    for (int t = 0; t < T_STEPS; t++) {
        // ---- prefetch next input tile into registers (hidden by gemm) ----
        const bool more = (t + 1 < T_STEPS);
        if (more) {
#pragma unroll
            for (int s = 0; s < NPF; s++) {
                int idx = tid + (s << 7);
                int r = idx >> KSH, k = idx & (KIN - 1);
                pin[s] = src[((size_t)((t + 1) * LLEN + row0 + r)) * KIN + k];
            }
        }

        // ---- gemm via FFMA2: 4 cols x 4 row-pairs per thread ----
        u64 A[16];
#pragma unroll
        for (int i = 0; i < 16; i++) A[i] = 0ull;
#pragma unroll 8
        for (int k = 0; k < NCACHE; k++) {          // cached weights (SMEM)
            float4 w = *(const float4*)&swc[k * G4H + (tid << 2)];
            u64 w0 = pack2(w.x), w1 = pack2(w.y), w2 = pack2(w.z), w3 = pack2(w.w);
            ulonglong2 ra = *(const ulonglong2*)&inT[k * 12];
            ulonglong2 rb = *(const ulonglong2*)&inT[k * 12 + 4];
            fma2(A[0],  ra.x, w0); fma2(A[1],  ra.y, w0);
            fma2(A[2],  rb.x, w0); fma2(A[3],  rb.y, w0);
            fma2(A[4],  ra.x, w1); fma2(A[5],  ra.y, w1);
            fma2(A[6],  rb.x, w1); fma2(A[7],  rb.y, w1);
            fma2(A[8],  ra.x, w2); fma2(A[9],  ra.y, w2);
            fma2(A[10], rb.x, w2); fma2(A[11], rb.y, w2);
            fma2(A[12], ra.x, w3); fma2(A[13], ra.y, w3);
            fma2(A[14], rb.x, w3); fma2(A[15], rb.y, w3);
        }
#pragma unroll 4
        for (int k = NCACHE; k < KTOT; k++) {       // streamed weights (L2)
            float4 w = *(const float4*)&wT[(size_t)k * G4H + (tid << 2)];
            u64 w0 = pack2(w.x), w1 = pack2(w.y), w2 = pack2(w.z), w3 = pack2(w.w);
            ulonglong2 ra = *(const ulonglong2*)&inT[k * 12];
            ulonglong2 rb = *(const ulonglong2*)&inT[k * 12 + 4];
            fma2(A[0],  ra.x, w0); fma2(A[1],  ra.y, w0);
            fma2(A[2],  rb.x, w0); fma2(A[3],  rb.y, w0);
            fma2(A[4],  ra.x, w1); fma2(A[5],  ra.y, w1);
            fma2(A[6],  rb.x, w1); fma2(A[7],  rb.y, w1);
            fma2(A[8],  ra.x, w2); fma2(A[9],  ra.y, w2);
            fma2(A[10], rb.x, w2); fma2(A[11], rb.y, w2);
            fma2(A[12], ra.x, w3); fma2(A[13], ra.y, w3);
            fma2(A[14], rb.x, w3); fma2(A[15], rb.y, w3);
        }
        // write gates: row-pair p holds rows 2p, 2p+1
#pragma unroll
        for (int p = 0; p < 4; p++) {
            float l0, h0, l1, h1, l2, h2, l3, h3;
            unpack2(l0, h0, A[p]);
            unpack2(l1, h1, A[4 + p]);
            unpack2(l2, h2, A[8 + p]);
            unpack2(l3, h3, A[12 + p]);
            float4 e0 = make_float4(l0 + bias.x, l1 + bias.y, l2 + bias.z, l3 + bias.w);
            float4 e1 = make_float4(h0 + bias.x, h1 + bias.y, h2 + bias.z, h3 + bias.w);
            *(float4*)&sG[(2 * p) * G4H + (tid << 2)] = e0;
            *(float4*)&sG[(2 * p + 1) * G4H + (tid << 2)] = e1;
        }
        __syncthreads();   // gates visible; gemm reads of inT complete

        // ---- store prefetched input (gemm done reading old inputs) ----
        if (more) {
#pragma unroll
            for (int s = 0; s < NPF; s++) {
                int idx = tid + (s << 7);
                int r = idx >> KSH, k = idx & (KIN - 1);
                inT[k * 12 + r] = pin[s];
            }
        }

        // ---- pointwise LSTM update (8 elements per thread) ----
#pragma unroll
        for (int s = 0; s < 8; s++) {
            int e = tid + (s << 7);
            int r = e >> 7, h = e & 127;
            float iv = sG[r * G4H + h];
            float fv = sG[r * G4H + H + h];
            float gv = sG[r * G4H + 2 * H + h];
            float ov = sG[r * G4H + 3 * H + h];
            float mem_old = inT[(KIN + h) * 12 + r];
            float reset = (mem_old - thr) > 0.f ? thr : 0.f;
            float syn_n = fsig(fv) * ssyn[e] + fsig(iv) * ftanh(gv);
            float mem_n = fsig(ov) * ftanh(syn_n) - reset;
            ssyn[e] = syn_n;
            inT[(KIN + h) * 12 + r] = mem_n;
            if (LAYER == 1)
                g_spk1[((size_t)(t * LLEN + row0 + r)) * H + h] =
                    (mem_n - thr) > 0.f ? 1.f : 0.f;
            else
                msum[e] += mem_n;
        }
        __syncthreads();   // inputs + mem visible before next gemm
    }

    if (LAYER == 2) {
        for (int e = tid; e < 8 * H; e += 128) {
            int r = e >> 7, h = e & 127;
            g_memsum[(row0 + r) * H + h] = msum[e];
        }
    }
}

// ---------------- BN stats: per-channel spike sums (deterministic) ----------
__global__ void __launch_bounds__(256) bn_stats() {
    __shared__ float sp[256];
    int tid = threadIdx.x;
    int h = tid & 127;
    int half = tid >> 7;
    float s = 0.f;
    size_t base = (size_t)blockIdx.x * LLEN * H;
    for (int rr = half; rr < LLEN; rr += 2)
        s += g_spk1[base + (size_t)rr * H + h];
    sp[tid] = s;
    __syncthreads();
    if (tid < 128) g_part[blockIdx.x * H + tid] = sp[tid] + sp[tid + 128];
}

// ---------------- BN fold: scale/shift -> weights + bias --------------------
__global__ void prep2a(const float* __restrict__ gamma, const float* __restrict__ beta) {
    int h = threadIdx.x;   // 128 threads
    float sum = 0.f;
    for (int b = 0; b < 256; b++) sum += g_part[b * H + h];
    float mu = sum / (float)M_TOT;
    float var = mu - mu * mu;              // binary data: E[x^2] = E[x]
    float a = gamma[h] * rsqrtf(var + 1e-5f);
    g_sa[h] = a;
    g_sbv[h] = beta[h] - mu * a;
}

__global__ void prep2b(const float* __restrict__ w_ih2) {
    int k = blockIdx.x;    // 128 blocks
    int j = threadIdx.x;   // 512 threads
    g_wc2T[k * G4H + j] = g_sa[k] * w_ih2[j * H + k];
}

__global__ void prep2c(const float* __restrict__ w_ih2, const float* __restrict__ b_ih2,
                       const float* __restrict__ b_hh2) {
    int j = threadIdx.x;   // 512 threads
    float b = b_ih2[j] + b_hh2[j];
#pragma unroll 8
    for (int k = 0; k < H; k++) b = fmaf(g_sbv[k], w_ih2[j * H + k], b);
    g_bias2[j] = b;
}

// ---------------- final FC --------------------------------------------------
__global__ void fc_kernel(const float* __restrict__ fc_w, const float* __restrict__ fc_b,
                          float* __restrict__ out) {
    int gid = blockIdx.x * blockDim.x + threadIdx.x;
    if (gid >= LLEN * NC) return;
    int l = gid / NC, n = gid % NC;
    float s = 0.f;
#pragma unroll 8
    for (int h = 0; h < H; h++) s = fmaf(g_memsum[l * H + h], fc_w[n * H + h], s);
    out[gid] = s * (1.0f / 256.0f) + fc_b[n];
}

// ---------------- launch ----------------------------------------------------
#define NCACHE1 96
#define NCACHE2 94

extern "C" void kernel_launch(void* const* d_in, const int* in_sizes, int n_in,
                              void* d_out, int out_size) {
    const float* x      = (const float*)d_in[0];
    const float* conv_w = (const float*)d_in[1];
    const float* conv_b = (const float*)d_in[2];
    const float* w_ih1  = (const float*)d_in[3];
    const float* w_hh1  = (const float*)d_in[4];
    const float* b_ih1  = (const float*)d_in[5];
    const float* b_hh1  = (const float*)d_in[6];
    const float* thr1   = (const float*)d_in[7];
    const float* w_ih2  = (const float*)d_in[8];
    const float* w_hh2  = (const float*)d_in[9];
    const float* b_ih2  = (const float*)d_in[10];
    const float* b_hh2  = (const float*)d_in[11];
    const float* thr2   = (const float*)d_in[12];
    const float* gamma  = (const float*)d_in[13];
    const float* beta   = (const float*)d_in[14];
    const float* fc_w   = (const float*)d_in[15];
    const float* fc_b   = (const float*)d_in[16];
    float* out = (float*)d_out;

    // dynamic smem sizes (bytes)
    const int smem1 = (NCACHE1 * G4H + (CCONV + H) * 12 + 8 * G4H + 16 * H) * 4;  // 228864
    const int smem2 = (NCACHE2 * G4H + (H + H) * 12 + 8 * G4H + 16 * H) * 4;      // 229376
    cudaFuncSetAttribute(scan_all<CCONV, 1, NCACHE1>,
                         cudaFuncAttributeMaxDynamicSharedMemorySize, smem1);
    cudaFuncSetAttribute(scan_all<H, 2, NCACHE2>,
                         cudaFuncAttributeMaxDynamicSharedMemorySize, smem2);

    prep0<<<128, 256>>>(w_ih1, w_hh1, b_ih1, b_hh1, w_hh2);
    conv_spike<<<M_TOT / 256, 256>>>(x, conv_w, conv_b);

    scan_all<CCONV, 1, NCACHE1><<<128, 128, smem1>>>(thr1);   // layer 1

    bn_stats<<<256, 256>>>();
    prep2a<<<1, 128>>>(gamma, beta);
    prep2b<<<128, 512>>>(w_ih2);
    prep2c<<<1, 512>>>(w_ih2, b_ih2, b_hh2);

    scan_all<H, 2, NCACHE2><<<128, 128, smem2>>>(thr2);       // layer 2

    fc_kernel<<<(LLEN * NC + 255) / 256, 256>>>(fc_w, fc_b, out);
}